// round 15
// baseline (speedup 1.0000x reference)
#include <cuda_runtime.h>

// Problem constants (SLEN=208, PTILE=8, STEP=2, EDGE=3, MAXDET=2)
#define BATCH 16
#define NSRC  100
#define NFLUX 5
#define NT    101                  // tiles per dim
#define PT    (NT * NT)            // 10201
#define BP    (BATCH * PT)         // 163216
// Output sections (float32, concatenated):
//   n [BP] | locs [BP*4] | fluxes [BP*10] | is_on [BP*2]
#define OFF_L (BP)                 // 163216  (mult of 4)
#define OFF_F (OFF_L + BP * 4)     // 816080  (mult of 4)
#define OFF_I (OFF_F + BP * 10)    // 2448240 (mult of 4)

#define TPB    256
#define NWARP  (TPB / 32)
#define CHUNK  276                         // mult of 4, < PT (spans <= 2 batches)
#define GRID   ((BP + CHUNK - 1) / CHUNK)  // 592: 4 blocks/SM, single wave

// Map pixel coords -> (tile, fx, fy); returns tile or -1.
// Exactly reproduces the reference: interval per dim is (2k+2.5, 2k+4.5),
// disjoint across k, so each source belongs to at most one tile. All
// constants (2k+2.5, scale=2) are exact in fp32 -> rel_err == 0.
__device__ __forceinline__ int map_source(float l0, float l1, float& fx, float& fy) {
    float p0 = l0 * 207.0f;                                  // SLEN-1
    float p1 = l1 * 207.0f;
    int kx = (int)floorf((p0 - 2.5f) * 0.5f);
    int ky = (int)floorf((p1 - 2.5f) * 0.5f);
    float lx = 2.0f * (float)kx + 2.5f;                      // exact fp32
    float ly = 2.0f * (float)ky + 2.5f;
    bool v0 = (kx >= 0) && (kx < NT) && (p0 > lx) && (p0 < lx + 2.0f) && (p0 != 0.0f);
    bool v1 = (ky >= 0) && (ky < NT) && (p1 > ly) && (p1 < ly + 2.0f) && (p1 != 0.0f);
    if (!(v0 && v1)) return -1;
    fx = (p0 - lx) * 0.5f;                                   // (lp - left)/scale, exact
    fy = (p1 - ly) * 0.5f;
    return kx * NT + ky;
}

__global__ __launch_bounds__(TPB)
void fused_kernel(const float* __restrict__ locs,
                  const float* __restrict__ fluxes,
                  float* __restrict__ out) {
    __shared__ int      s_g[TPB];       // cell id per slot (valid iff ballot bit set)
    __shared__ unsigned s_mask[NWARP];  // per-warp acceptance ballots

    const int t  = threadIdx.x;
    const int g0 = blockIdx.x * CHUNK;
    const int g1 = min(g0 + CHUNK, BP);
    const int n  = g1 - g0;             // multiple of 4 (last block: 100)

    // ---- front-issue ALL input loads unconditionally (clamped index):
    //      7 LDGs in flight at MLP=7 from cycle 0, overlapping the fill ----
    const int b_lo = g0 / PT;
    const int b_hi = (g1 - 1) / PT;                // <= b_lo + 1
    const int i_lo = b_lo * NSRC;
    const int span = (b_hi + 1) * NSRC - i_lo;     // <= 200 <= TPB
    const bool has = (t < span);
    const int idx  = i_lo + (has ? t : 0);         // clamp: safe, unused if !has
    const float2 l = __ldg(&((const float2*)locs)[idx]);   // 8B-aligned (idx*8)
    const float* __restrict__ fl = fluxes + idx * NFLUX;
    const float fv0 = __ldg(fl + 0);
    const float fv1 = __ldg(fl + 1);
    const float fv2 = __ldg(fl + 2);
    const float fv3 = __ldg(fl + 3);
    const float fv4 = __ldg(fl + 4);

    // ---- Phase A: zero the 4 per-section slices; <=7 predicated STG.128 ----
    {
        const float4 z = make_float4(0.f, 0.f, 0.f, 0.f);
        float4* __restrict__ pN = (float4*)(out + g0);
        float4* __restrict__ pL = (float4*)(out + OFF_L + 4  * g0);
        float4* __restrict__ pF = (float4*)(out + OFF_F + 10 * g0);
        float4* __restrict__ pI = (float4*)(out + OFF_I + 2  * g0);
        const int cN = n >> 2;          // <= 69
        const int cL = n;               // <= 276
        const int cF = (10 * n) >> 2;   // <= 690
        const int cI = n >> 1;          // <= 138
        if (t           < cN) pN[t]           = z;
        if (t           < cL) pL[t]           = z;
        if (t + TPB     < cL) pL[t + TPB]     = z;
        if (t           < cF) pF[t]           = z;
        if (t + TPB     < cF) pF[t + TPB]     = z;
        if (t + 2 * TPB < cF) pF[t + 2 * TPB] = z;
        if (t           < cI) pI[t]           = z;
    }

    // ---- Phase B: classify (no atomics). Slot = thread id. ----
    float fx = 0.f, fy = 0.f;
    int   g  = -1;
    if (has) {
        int tile = map_source(l.x, l.y, fx, fy);
        if (tile >= 0) {
            int b = b_lo + (t >= NSRC ? 1 : 0);    // idx/NSRC without divide
            int gg = b * PT + tile;
            if (gg >= g0 && gg < g1) g = gg;
        }
    }
    const bool acc = (g >= 0);
    unsigned m = __ballot_sync(0xFFFFFFFFu, acc);
    if ((t & 31) == 0) s_mask[t >> 5] = m;         // every warp publishes
    if (acc) s_g[t] = g;                           // only accepted slots are read

    __syncthreads();   // ONE barrier: shared visibility + zero/payload WAW order

    // ---- Phase C: rank by walking the ~14 mask bits; payload from registers.
    //      Rank among same-cell sources by source index == reference's stable
    //      argsort order; rank<MAXDET sources fill slots 0/1. ----
    if (acc) {
        int count = 0, rank = 0;
        #pragma unroll
        for (int w = 0; w < NWARP; w++) {
            unsigned mw = s_mask[w];
            while (mw) {
                int bi = __ffs(mw) - 1;
                mw &= mw - 1;
                int j  = (w << 5) + bi;
                if (s_g[j] == g) { count++; rank += (j < t); }
            }
        }

        if (rank == 0)
            out[g] = (float)(count < 2 ? count : 2);     // min(n, MAXDET)

        if (rank < 2) {
            *(float2*)(out + OFF_L + 4 * g + 2 * rank) = make_float2(fx, fy);

            int fb = OFF_F + 10 * g + 5 * rank;    // base only 4B-aligned: scalars
            out[fb + 0] = fv0;
            out[fb + 1] = fv1;
            out[fb + 2] = fv2;
            out[fb + 3] = fv3;
            out[fb + 4] = fv4;

            out[OFF_I + 2 * g + rank] = 1.0f;
        }
    }
}

extern "C" void kernel_launch(void* const* d_in, const int* in_sizes, int n_in,
                              void* d_out, int out_size) {
    const float* locs   = (const float*)d_in[0];   // (16, 100, 2) f32
    const float* fluxes = (const float*)d_in[1];   // (16, 100, 5) f32
    fused_kernel<<<GRID, TPB>>>(locs, fluxes, (float*)d_out);
}

// round 16
// speedup vs baseline: 1.3413x; 1.3413x over previous
#include <cuda_runtime.h>

// Problem constants (SLEN=208, PTILE=8, STEP=2, EDGE=3, MAXDET=2)
#define BATCH 16
#define NSRC  100
#define NFLUX 5
#define NT    101                  // tiles per dim
#define PT    (NT * NT)            // 10201
#define BP    (BATCH * PT)         // 163216
// Output sections (float32, concatenated):
//   n [BP] | locs [BP*4] | fluxes [BP*10] | is_on [BP*2]
#define OFF_L (BP)                 // 163216  (mult of 4)
#define OFF_F (OFF_L + BP * 4)     // 816080  (mult of 4)
#define OFF_I (OFF_F + BP * 10)    // 2448240 (mult of 4)

#define TPB    256
#define NWARP  (TPB / 32)
#define CHUNK  276                         // mult of 4, < PT (spans <= 2 batches)
#define GRID   ((BP + CHUNK - 1) / CHUNK)  // 592: 4 blocks/SM, single wave

// Map pixel coords -> (tile, fx, fy); returns tile or -1.
// Exactly reproduces the reference: interval per dim is (2k+2.5, 2k+4.5),
// disjoint across k, so each source belongs to at most one tile. All
// constants (2k+2.5, scale=2) are exact in fp32 -> rel_err == 0.
__device__ __forceinline__ int map_source(float l0, float l1, float& fx, float& fy) {
    float p0 = l0 * 207.0f;                                  // SLEN-1
    float p1 = l1 * 207.0f;
    int kx = (int)floorf((p0 - 2.5f) * 0.5f);
    int ky = (int)floorf((p1 - 2.5f) * 0.5f);
    float lx = 2.0f * (float)kx + 2.5f;                      // exact fp32
    float ly = 2.0f * (float)ky + 2.5f;
    bool v0 = (kx >= 0) && (kx < NT) && (p0 > lx) && (p0 < lx + 2.0f) && (p0 != 0.0f);
    bool v1 = (ky >= 0) && (ky < NT) && (p1 > ly) && (p1 < ly + 2.0f) && (p1 != 0.0f);
    if (!(v0 && v1)) return -1;
    fx = (p0 - lx) * 0.5f;                                   // (lp - left)/scale, exact
    fy = (p1 - ly) * 0.5f;
    return kx * NT + ky;
}

__global__ __launch_bounds__(TPB)
void fused_kernel(const float* __restrict__ locs,
                  const float* __restrict__ fluxes,
                  float* __restrict__ out) {
    __shared__ int      s_g[TPB];       // cell id per slot (valid iff ballot bit set)
    __shared__ unsigned s_mask[NWARP];  // per-warp acceptance ballots

    const int t  = threadIdx.x;
    const int g0 = blockIdx.x * CHUNK;
    const int g1 = min(g0 + CHUNK, BP);
    const int n  = g1 - g0;             // multiple of 4 (last block: 100)

    // ---- front-issue ALL input loads unconditionally (clamped index):
    //      7 LDGs in flight at MLP=7 from cycle 0, overlapping the fill ----
    const int b_lo = g0 / PT;
    const int b_hi = (g1 - 1) / PT;                // <= b_lo + 1
    const int i_lo = b_lo * NSRC;
    const int span = (b_hi + 1) * NSRC - i_lo;     // <= 200 <= TPB
    const bool has = (t < span);
    const int idx  = i_lo + (has ? t : 0);         // clamp: safe, unused if !has
    const float2 l = __ldg(&((const float2*)locs)[idx]);   // 8B-aligned (idx*8)
    const float* __restrict__ fl = fluxes + idx * NFLUX;
    const float fv0 = __ldg(fl + 0);
    const float fv1 = __ldg(fl + 1);
    const float fv2 = __ldg(fl + 2);
    const float fv3 = __ldg(fl + 3);
    const float fv4 = __ldg(fl + 4);

    // ---- Phase A: zero the 4 per-section slices; <=7 predicated STG.128 ----
    {
        const float4 z = make_float4(0.f, 0.f, 0.f, 0.f);
        float4* __restrict__ pN = (float4*)(out + g0);
        float4* __restrict__ pL = (float4*)(out + OFF_L + 4  * g0);
        float4* __restrict__ pF = (float4*)(out + OFF_F + 10 * g0);
        float4* __restrict__ pI = (float4*)(out + OFF_I + 2  * g0);
        const int cN = n >> 2;          // <= 69
        const int cL = n;               // <= 276
        const int cF = (10 * n) >> 2;   // <= 690
        const int cI = n >> 1;          // <= 138
        if (t           < cN) pN[t]           = z;
        if (t           < cL) pL[t]           = z;
        if (t + TPB     < cL) pL[t + TPB]     = z;
        if (t           < cF) pF[t]           = z;
        if (t + TPB     < cF) pF[t + TPB]     = z;
        if (t + 2 * TPB < cF) pF[t + 2 * TPB] = z;
        if (t           < cI) pI[t]           = z;
    }

    // ---- Phase B: classify (no atomics). Slot = thread id. ----
    float fx = 0.f, fy = 0.f;
    int   g  = -1;
    if (has) {
        int tile = map_source(l.x, l.y, fx, fy);
        if (tile >= 0) {
            int b = b_lo + (t >= NSRC ? 1 : 0);    // idx/NSRC without divide
            int gg = b * PT + tile;
            if (gg >= g0 && gg < g1) g = gg;
        }
    }
    const bool acc = (g >= 0);
    unsigned m = __ballot_sync(0xFFFFFFFFu, acc);
    if ((t & 31) == 0) s_mask[t >> 5] = m;         // every warp publishes
    if (acc) s_g[t] = g;                           // only accepted slots are read

    __syncthreads();   // ONE barrier: shared visibility + zero/payload WAW order

    // ---- Phase C: rank by walking the ~14 mask bits; payload from registers.
    //      Rank among same-cell sources by source index == reference's stable
    //      argsort order; rank<MAXDET sources fill slots 0/1. ----
    if (acc) {
        int count = 0, rank = 0;
        #pragma unroll
        for (int w = 0; w < NWARP; w++) {
            unsigned mw = s_mask[w];
            while (mw) {
                int bi = __ffs(mw) - 1;
                mw &= mw - 1;
                int j  = (w << 5) + bi;
                if (s_g[j] == g) { count++; rank += (j < t); }
            }
        }

        if (rank == 0)
            out[g] = (float)(count < 2 ? count : 2);     // min(n, MAXDET)

        if (rank < 2) {
            *(float2*)(out + OFF_L + 4 * g + 2 * rank) = make_float2(fx, fy);

            int fb = OFF_F + 10 * g + 5 * rank;    // base only 4B-aligned: scalars
            out[fb + 0] = fv0;
            out[fb + 1] = fv1;
            out[fb + 2] = fv2;
            out[fb + 3] = fv3;
            out[fb + 4] = fv4;

            out[OFF_I + 2 * g + rank] = 1.0f;
        }
    }
}

extern "C" void kernel_launch(void* const* d_in, const int* in_sizes, int n_in,
                              void* d_out, int out_size) {
    const float* locs   = (const float*)d_in[0];   // (16, 100, 2) f32
    const float* fluxes = (const float*)d_in[1];   // (16, 100, 5) f32
    fused_kernel<<<GRID, TPB>>>(locs, fluxes, (float*)d_out);
}